// round 12
// baseline (speedup 1.0000x reference)
#include <cuda_runtime.h>
#include <math.h>

#define SQ2H 0.70710678118654752440f

// 128 MB intermediate: [8][64][256][256]
__device__ float g_mid[(size_t)8 * 64 * 256 * 256];

__device__ __forceinline__ float gelu_f(float v) { return v * normcdff(v); }

// ---------------------------------------------------------------------------
// Kernel 1: 1x1 conv (32->64) + per-8x8-patch rFFT2 * fft1 -> GELU -> * fft2
//           -> irFFT2, writes g_mid.
// Grid: (1024, 8) = (Hp*Wp, B). Block: 512 threads.
// ---------------------------------------------------------------------------
__global__ __launch_bounds__(512) void k1_fft(
    const float* __restrict__ x, const float* __restrict__ w_in,
    const float* __restrict__ b_in, const float* __restrict__ fft1,
    const float* __restrict__ fft2)
{
    __shared__ __align__(16) float s_in[32 * 64];   // [c][y*8+x]
    __shared__ float s_w[32 * 65];                  // [c][c2], padded
    __shared__ float s_fr[64 * 41];                 // padded per-channel
    __shared__ float s_fi[64 * 41];

    const int tid = threadIdx.x;
    const int hp = blockIdx.x >> 5, wp = blockIdx.x & 31;
    const int b = blockIdx.y;

    // load 32x8x8 input patch (each thread: one float4)
    {
        int c = tid >> 4, rem = tid & 15;
        int py = rem >> 1, half = rem & 1;
        const float4* src = reinterpret_cast<const float4*>(
            x + ((((size_t)b * 32 + c) * 256 + hp * 8 + py) * 256 + wp * 8)) + half;
        reinterpret_cast<float4*>(s_in)[c * 16 + py * 2 + half] = *src;
    }
    // load w_in transposed: s_w[c][c2]
    for (int i = tid; i < 64 * 32; i += 512) {
        int c2 = i >> 5, c = i & 31;
        s_w[c * 65 + c2] = w_in[i];
    }
    __syncthreads();

    // -------- phase 1: conv 1x1 + forward real row FFT (per (c2, y)) --------
    {
        const int c2 = tid & 63, y = tid >> 6;
        float bias = __ldg(b_in + c2);
        float a[8];
#pragma unroll
        for (int k = 0; k < 8; k++) a[k] = bias;
#pragma unroll
        for (int c = 0; c < 32; c++) {
            float w = s_w[c * 65 + c2];
            const float4* rp = reinterpret_cast<const float4*>(s_in + c * 64 + y * 8);
            float4 r0 = rp[0], r1 = rp[1];
            a[0] = fmaf(w, r0.x, a[0]); a[1] = fmaf(w, r0.y, a[1]);
            a[2] = fmaf(w, r0.z, a[2]); a[3] = fmaf(w, r0.w, a[3]);
            a[4] = fmaf(w, r1.x, a[4]); a[5] = fmaf(w, r1.y, a[5]);
            a[6] = fmaf(w, r1.z, a[6]); a[7] = fmaf(w, r1.w, a[7]);
        }
        // 8-pt real FFT -> F[0..4]
        float p02 = a[0] + a[4], m02 = a[0] - a[4];
        float p13 = a[2] + a[6], m13 = a[2] - a[6];
        float E0 = p02 + p13, E2 = p02 - p13;
        float E1r = m02, E1i = -m13;
        float q02 = a[1] + a[5], n02 = a[1] - a[5];
        float q13 = a[3] + a[7], n13 = a[3] - a[7];
        float O0 = q02 + q13, O2 = q02 - q13;
        float O1r = n02, O1i = -n13;
        float t1 = SQ2H * (O1r + O1i), t2 = SQ2H * (O1i - O1r);
        float* fr = s_fr + c2 * 41 + y;
        float* fi = s_fi + c2 * 41 + y;
        fr[0]  = E0 + O0;   fi[0]  = 0.f;
        fr[8]  = E1r + t1;  fi[8]  = E1i + t2;
        fr[16] = E2;        fi[16] = -O2;
        fr[24] = E1r - t1;  fi[24] = -E1i + t2;
        fr[32] = E0 - O0;   fi[32] = 0.f;
    }
    __syncthreads();

    // -------- phase 2: column complex FFT + filter/gelu + inverse ----------
    {
        const int cc = tid >> 3, j = tid & 7;
        float gr[8], gi[8];
        if (j < 5) {
            float zr[8], zi[8];
            {
                const float* fr = s_fr + cc * 41 + j * 8;
                const float* fi = s_fi + cc * 41 + j * 8;
#pragma unroll
                for (int yy = 0; yy < 8; yy++) { zr[yy] = fr[yy]; zi[yy] = fi[yy]; }
            }
            float Fr[8], Fi[8];
            {   // forward 8-pt complex FFT
                float t0r = zr[0] + zr[4], t0i = zi[0] + zi[4];
                float t1r = zr[0] - zr[4], t1i = zi[0] - zi[4];
                float t2r = zr[2] + zr[6], t2i = zi[2] + zi[6];
                float t3r = zr[2] - zr[6], t3i = zi[2] - zi[6];
                float E0r = t0r + t2r, E0i = t0i + t2i;
                float E2r = t0r - t2r, E2i = t0i - t2i;
                float E1r = t1r + t3i, E1i = t1i - t3r;   // t1 - i*t3
                float E3r = t1r - t3i, E3i = t1i + t3r;   // t1 + i*t3
                float s0r = zr[1] + zr[5], s0i = zi[1] + zi[5];
                float s1r = zr[1] - zr[5], s1i = zi[1] - zi[5];
                float s2r = zr[3] + zr[7], s2i = zi[3] + zi[7];
                float s3r = zr[3] - zr[7], s3i = zi[3] - zi[7];
                float O0r = s0r + s2r, O0i = s0i + s2i;
                float O2r = s0r - s2r, O2i = s0i - s2i;
                float O1r = s1r + s3i, O1i = s1i - s3r;
                float O3r = s1r - s3i, O3i = s1i + s3r;
                float w1r = SQ2H * (O1r + O1i), w1i = SQ2H * (O1i - O1r);
                float w2r = O2i,                w2i = -O2r;
                float w3r = SQ2H * (O3i - O3r), w3i = -SQ2H * (O3r + O3i);
                Fr[0] = E0r + O0r; Fi[0] = E0i + O0i;
                Fr[4] = E0r - O0r; Fi[4] = E0i - O0i;
                Fr[1] = E1r + w1r; Fi[1] = E1i + w1i;
                Fr[5] = E1r - w1r; Fi[5] = E1i - w1i;
                Fr[2] = E2r + w2r; Fi[2] = E2i + w2i;
                Fr[6] = E2r - w2r; Fi[6] = E2i - w2i;
                Fr[3] = E3r + w3r; Fi[3] = E3i + w3i;
                Fr[7] = E3r - w3r; Fi[7] = E3i - w3i;
            }
            {   // spectral filter + exact GELU + filter2 (fold 1/64)
                const float* f1p = fft1 + cc * 40 + j;
                const float* f2p = fft2 + cc * 40 + j;
#pragma unroll
                for (int ky = 0; ky < 8; ky++) {
                    float s1 = __ldg(f1p + ky * 5);
                    float ar = gelu_f(Fr[ky] * s1);
                    float ai = gelu_f(Fi[ky] * s1);
                    float s2 = __ldg(f2p + ky * 5) * 0.015625f;  // 1/64
                    Fr[ky] = ar * s2; Fi[ky] = ai * s2;
                }
            }
            {   // inverse 8-pt complex FFT (unscaled)
                float t0r = Fr[0] + Fr[4], t0i = Fi[0] + Fi[4];
                float t1r = Fr[0] - Fr[4], t1i = Fi[0] - Fi[4];
                float t2r = Fr[2] + Fr[6], t2i = Fi[2] + Fi[6];
                float t3r = Fr[2] - Fr[6], t3i = Fi[2] - Fi[6];
                float E0r = t0r + t2r, E0i = t0i + t2i;
                float E2r = t0r - t2r, E2i = t0i - t2i;
                float E1r = t1r - t3i, E1i = t1i + t3r;   // t1 + i*t3
                float E3r = t1r + t3i, E3i = t1i - t3r;   // t1 - i*t3
                float s0r = Fr[1] + Fr[5], s0i = Fi[1] + Fi[5];
                float s1r = Fr[1] - Fr[5], s1i = Fi[1] - Fi[5];
                float s2r = Fr[3] + Fr[7], s2i = Fi[3] + Fi[7];
                float s3r = Fr[3] - Fr[7], s3i = Fi[3] - Fi[7];
                float O0r = s0r + s2r, O0i = s0i + s2i;
                float O2r = s0r - s2r, O2i = s0i - s2i;
                float O1r = s1r - s3i, O1i = s1i + s3r;
                float O3r = s1r + s3i, O3i = s1i - s3r;
                float w1r = SQ2H * (O1r - O1i), w1i = SQ2H * (O1r + O1i);
                float w2r = -O2i,               w2i = O2r;
                float w3r = -SQ2H * (O3r + O3i), w3i = SQ2H * (O3r - O3i);
                gr[0] = E0r + O0r; gi[0] = E0i + O0i;
                gr[4] = E0r - O0r; gi[4] = E0i - O0i;
                gr[1] = E1r + w1r; gi[1] = E1i + w1i;
                gr[5] = E1r - w1r; gi[5] = E1i - w1i;
                gr[2] = E2r + w2r; gi[2] = E2i + w2i;
                gr[6] = E2r - w2r; gi[6] = E2i - w2i;
                gr[3] = E3r + w3r; gi[3] = E3i + w3i;
                gr[7] = E3r - w3r; gi[7] = E3i - w3i;
            }
        }
        __syncthreads();   // reads done before relayout writes
        if (j < 5) {
            float* fr = s_fr + cc * 41 + j;
            float* fi = s_fi + cc * 41 + j;
#pragma unroll
            for (int yy = 0; yy < 8; yy++) { fr[yy * 5] = gr[yy]; fi[yy * 5] = gi[yy]; }
        }
    }
    __syncthreads();

    // -------- phase 3: inverse real row FFT (C2R) + store ------------------
    {
        const int c2 = tid & 63, y = tid >> 6;
        const float* fr = s_fr + c2 * 41 + y * 5;
        const float* fi = s_fi + c2 * 41 + y * 5;
        float G0r = fr[0];
        float G1r = fr[1], G1i = fi[1];
        float G2r = fr[2], G2i = fi[2];
        float G3r = fr[3], G3i = fi[3];
        float G4r = fr[4];
        float A1r = 2.f * G1r, A1i = 2.f * G1i;
        float A2r = 2.f * G2r, A2i = 2.f * G2i;
        float A3r = 2.f * G3r, A3i = 2.f * G3i;
        float B0 = G0r + G4r, B1 = G0r - G4r;
        float u = SQ2H * (A1r - A1i), v = SQ2H * (A3r + A3i);
        float p = SQ2H * (A1r + A1i), q = SQ2H * (A3r - A3i);
        float x0 = B0 + A1r + A2r + A3r;
        float x4 = B0 - A1r + A2r - A3r;
        float x2 = B0 - A2r - A1i + A3i;
        float x6 = B0 - A2r + A1i - A3i;
        float x1 = B1 + u - A2i - v;
        float x3 = B1 - p + A2i + q;
        float x5 = B1 - u - A2i + v;
        float x7 = B1 + p + A2i - q;
        float4* dst = reinterpret_cast<float4*>(
            g_mid + (((((size_t)b * 64 + c2) * 256) + hp * 8 + y) * 256 + wp * 8));
        dst[0] = make_float4(x0, x1, x2, x3);
        dst[1] = make_float4(x4, x5, x6, x7);
    }
}

// ---------------------------------------------------------------------------
// Kernel 2: 7x7 depthwise conv (pad 3) + GELU + 1x1 conv (64->32).
// Grid: (16, 16, 8). Block: 256 threads = 16x16 tile; 32 out-ch accumulators.
// ---------------------------------------------------------------------------
__global__ __launch_bounds__(256) void k2_dwout(
    const float* __restrict__ w_dw, const float* __restrict__ b_dw,
    const float* __restrict__ w_out, const float* __restrict__ b_out,
    float* __restrict__ out)
{
    __shared__ float s_halo[22 * 48];
    __shared__ float s_wdw[64 * 49];
    __shared__ float s_wout[64 * 33];   // [c2][co], padded
    __shared__ float s_bdw[64];
    __shared__ float s_bout[32];

    const int tid = threadIdx.x;
    for (int i = tid; i < 64 * 49; i += 256) s_wdw[i] = w_dw[i];
    for (int i = tid; i < 64 * 32; i += 256) {
        int co = i >> 6, c2 = i & 63;
        s_wout[c2 * 33 + co] = w_out[i];
    }
    if (tid < 64) s_bdw[tid] = b_dw[tid];
    if (tid < 32) s_bout[tid] = b_out[tid];

    const int ty = tid >> 4, tx = tid & 15;
    const int w0 = blockIdx.x << 4, h0 = blockIdx.y << 4, b = blockIdx.z;
    const float* midb = g_mid + (size_t)b * 64 * 65536;

    float acc[32];
#pragma unroll
    for (int co = 0; co < 32; co++) acc[co] = 0.f;

    for (int c2 = 0; c2 < 64; c2++) {
        __syncthreads();   // also covers weight-staging before first iter
        const float* src = midb + (size_t)c2 * 65536;
        for (int i = tid; i < 484; i += 256) {
            int r = i / 22, cl = i - r * 22;
            int hh = h0 - 3 + r, ww = w0 - 3 + cl;
            float val = 0.f;
            if ((unsigned)hh < 256u && (unsigned)ww < 256u)
                val = __ldg(src + hh * 256 + ww);
            s_halo[r * 48 + cl] = val;
        }
        __syncthreads();

        float v = s_bdw[c2];
        const float* wd = s_wdw + c2 * 49;
#pragma unroll
        for (int ky = 0; ky < 7; ky++) {
            const float* hrow = s_halo + (ty + ky) * 48 + tx;
#pragma unroll
            for (int kx = 0; kx < 7; kx++)
                v = fmaf(wd[ky * 7 + kx], hrow[kx], v);
        }
        float gv = v * normcdff(v);
        const float* wo = s_wout + c2 * 33;
#pragma unroll
        for (int co = 0; co < 32; co++)
            acc[co] = fmaf(wo[co], gv, acc[co]);
    }

    const int hh = h0 + ty, ww = w0 + tx;
    float* op = out + (size_t)b * 32 * 65536 + hh * 256 + ww;
#pragma unroll
    for (int co = 0; co < 32; co++)
        op[(size_t)co * 65536] = acc[co] + s_bout[co];
}

// ---------------------------------------------------------------------------
extern "C" void kernel_launch(void* const* d_in, const int* in_sizes, int n_in,
                              void* d_out, int out_size)
{
    const float* x     = (const float*)d_in[0];
    const float* w_in  = (const float*)d_in[1];
    const float* b_in  = (const float*)d_in[2];
    const float* fft1  = (const float*)d_in[3];
    const float* fft2  = (const float*)d_in[4];
    const float* w_dw  = (const float*)d_in[5];
    const float* b_dw  = (const float*)d_in[6];
    const float* w_out = (const float*)d_in[7];
    const float* b_out = (const float*)d_in[8];
    float* out = (float*)d_out;

    dim3 g1(1024, 8);
    k1_fft<<<g1, 512>>>(x, w_in, b_in, fft1, fft2);
    dim3 g2(16, 16, 8);
    k2_dwout<<<g2, 256>>>(w_dw, b_dw, w_out, b_out, out);
}

// round 13
// speedup vs baseline: 1.0026x; 1.0026x over previous
#include <cuda_runtime.h>
#include <math.h>

#define SQ2H 0.70710678118654752440f

// 128 MB intermediate: [8][64][256][256]
__device__ float g_mid[(size_t)8 * 64 * 256 * 256];

__device__ __forceinline__ float gelu_f(float v) { return v * normcdff(v); }

// ---------------------------------------------------------------------------
// Kernel 1: 1x1 conv (32->64) + per-8x8-patch rFFT2 * fft1 -> GELU -> * fft2
//           -> irFFT2, writes g_mid.
// Grid: (1024, 8) = (Hp*Wp, B). Block: 512 threads.
// ---------------------------------------------------------------------------
__global__ __launch_bounds__(512) void k1_fft(
    const float* __restrict__ x, const float* __restrict__ w_in,
    const float* __restrict__ b_in, const float* __restrict__ fft1,
    const float* __restrict__ fft2)
{
    __shared__ __align__(16) float s_in[32 * 64];   // [c][y*8+x]
    __shared__ float s_w[32 * 65];                  // [c][c2], padded
    __shared__ float s_fr[64 * 41];                 // padded per-channel
    __shared__ float s_fi[64 * 41];

    const int tid = threadIdx.x;
    const int hp = blockIdx.x >> 5, wp = blockIdx.x & 31;
    const int b = blockIdx.y;

    // load 32x8x8 input patch (each thread: one float4)
    {
        int c = tid >> 4, rem = tid & 15;
        int py = rem >> 1, half = rem & 1;
        const float4* src = reinterpret_cast<const float4*>(
            x + ((((size_t)b * 32 + c) * 256 + hp * 8 + py) * 256 + wp * 8)) + half;
        reinterpret_cast<float4*>(s_in)[c * 16 + py * 2 + half] = *src;
    }
    // load w_in transposed: s_w[c][c2]
    for (int i = tid; i < 64 * 32; i += 512) {
        int c2 = i >> 5, c = i & 31;
        s_w[c * 65 + c2] = w_in[i];
    }
    __syncthreads();

    // -------- phase 1: conv 1x1 + forward real row FFT (per (c2, y)) --------
    {
        const int c2 = tid & 63, y = tid >> 6;
        float bias = __ldg(b_in + c2);
        float a[8];
#pragma unroll
        for (int k = 0; k < 8; k++) a[k] = bias;
#pragma unroll
        for (int c = 0; c < 32; c++) {
            float w = s_w[c * 65 + c2];
            const float4* rp = reinterpret_cast<const float4*>(s_in + c * 64 + y * 8);
            float4 r0 = rp[0], r1 = rp[1];
            a[0] = fmaf(w, r0.x, a[0]); a[1] = fmaf(w, r0.y, a[1]);
            a[2] = fmaf(w, r0.z, a[2]); a[3] = fmaf(w, r0.w, a[3]);
            a[4] = fmaf(w, r1.x, a[4]); a[5] = fmaf(w, r1.y, a[5]);
            a[6] = fmaf(w, r1.z, a[6]); a[7] = fmaf(w, r1.w, a[7]);
        }
        // 8-pt real FFT -> F[0..4]
        float p02 = a[0] + a[4], m02 = a[0] - a[4];
        float p13 = a[2] + a[6], m13 = a[2] - a[6];
        float E0 = p02 + p13, E2 = p02 - p13;
        float E1r = m02, E1i = -m13;
        float q02 = a[1] + a[5], n02 = a[1] - a[5];
        float q13 = a[3] + a[7], n13 = a[3] - a[7];
        float O0 = q02 + q13, O2 = q02 - q13;
        float O1r = n02, O1i = -n13;
        float t1 = SQ2H * (O1r + O1i), t2 = SQ2H * (O1i - O1r);
        float* fr = s_fr + c2 * 41 + y;
        float* fi = s_fi + c2 * 41 + y;
        fr[0]  = E0 + O0;   fi[0]  = 0.f;
        fr[8]  = E1r + t1;  fi[8]  = E1i + t2;
        fr[16] = E2;        fi[16] = -O2;
        fr[24] = E1r - t1;  fi[24] = -E1i + t2;
        fr[32] = E0 - O0;   fi[32] = 0.f;
    }
    __syncthreads();

    // -------- phase 2: column complex FFT + filter/gelu + inverse ----------
    {
        const int cc = tid >> 3, j = tid & 7;
        float gr[8], gi[8];
        if (j < 5) {
            float zr[8], zi[8];
            {
                const float* fr = s_fr + cc * 41 + j * 8;
                const float* fi = s_fi + cc * 41 + j * 8;
#pragma unroll
                for (int yy = 0; yy < 8; yy++) { zr[yy] = fr[yy]; zi[yy] = fi[yy]; }
            }
            float Fr[8], Fi[8];
            {   // forward 8-pt complex FFT
                float t0r = zr[0] + zr[4], t0i = zi[0] + zi[4];
                float t1r = zr[0] - zr[4], t1i = zi[0] - zi[4];
                float t2r = zr[2] + zr[6], t2i = zi[2] + zi[6];
                float t3r = zr[2] - zr[6], t3i = zi[2] - zi[6];
                float E0r = t0r + t2r, E0i = t0i + t2i;
                float E2r = t0r - t2r, E2i = t0i - t2i;
                float E1r = t1r + t3i, E1i = t1i - t3r;   // t1 - i*t3
                float E3r = t1r - t3i, E3i = t1i + t3r;   // t1 + i*t3
                float s0r = zr[1] + zr[5], s0i = zi[1] + zi[5];
                float s1r = zr[1] - zr[5], s1i = zi[1] - zi[5];
                float s2r = zr[3] + zr[7], s2i = zi[3] + zi[7];
                float s3r = zr[3] - zr[7], s3i = zi[3] - zi[7];
                float O0r = s0r + s2r, O0i = s0i + s2i;
                float O2r = s0r - s2r, O2i = s0i - s2i;
                float O1r = s1r + s3i, O1i = s1i - s3r;
                float O3r = s1r - s3i, O3i = s1i + s3r;
                float w1r = SQ2H * (O1r + O1i), w1i = SQ2H * (O1i - O1r);
                float w2r = O2i,                w2i = -O2r;
                float w3r = SQ2H * (O3i - O3r), w3i = -SQ2H * (O3r + O3i);
                Fr[0] = E0r + O0r; Fi[0] = E0i + O0i;
                Fr[4] = E0r - O0r; Fi[4] = E0i - O0i;
                Fr[1] = E1r + w1r; Fi[1] = E1i + w1i;
                Fr[5] = E1r - w1r; Fi[5] = E1i - w1i;
                Fr[2] = E2r + w2r; Fi[2] = E2i + w2i;
                Fr[6] = E2r - w2r; Fi[6] = E2i - w2i;
                Fr[3] = E3r + w3r; Fi[3] = E3i + w3i;
                Fr[7] = E3r - w3r; Fi[7] = E3i - w3i;
            }
            {   // spectral filter + exact GELU + filter2 (fold 1/64)
                const float* f1p = fft1 + cc * 40 + j;
                const float* f2p = fft2 + cc * 40 + j;
#pragma unroll
                for (int ky = 0; ky < 8; ky++) {
                    float s1 = __ldg(f1p + ky * 5);
                    float ar = gelu_f(Fr[ky] * s1);
                    float ai = gelu_f(Fi[ky] * s1);
                    float s2 = __ldg(f2p + ky * 5) * 0.015625f;  // 1/64
                    Fr[ky] = ar * s2; Fi[ky] = ai * s2;
                }
            }
            {   // inverse 8-pt complex FFT (unscaled)
                float t0r = Fr[0] + Fr[4], t0i = Fi[0] + Fi[4];
                float t1r = Fr[0] - Fr[4], t1i = Fi[0] - Fi[4];
                float t2r = Fr[2] + Fr[6], t2i = Fi[2] + Fi[6];
                float t3r = Fr[2] - Fr[6], t3i = Fi[2] - Fi[6];
                float E0r = t0r + t2r, E0i = t0i + t2i;
                float E2r = t0r - t2r, E2i = t0i - t2i;
                float E1r = t1r - t3i, E1i = t1i + t3r;   // t1 + i*t3
                float E3r = t1r + t3i, E3i = t1i - t3r;   // t1 - i*t3
                float s0r = Fr[1] + Fr[5], s0i = Fi[1] + Fi[5];
                float s1r = Fr[1] - Fr[5], s1i = Fi[1] - Fi[5];
                float s2r = Fr[3] + Fr[7], s2i = Fi[3] + Fi[7];
                float s3r = Fr[3] - Fr[7], s3i = Fi[3] - Fi[7];
                float O0r = s0r + s2r, O0i = s0i + s2i;
                float O2r = s0r - s2r, O2i = s0i - s2i;
                float O1r = s1r - s3i, O1i = s1i + s3r;
                float O3r = s1r + s3i, O3i = s1i - s3r;
                float w1r = SQ2H * (O1r - O1i), w1i = SQ2H * (O1r + O1i);
                float w2r = -O2i,               w2i = O2r;
                float w3r = -SQ2H * (O3r + O3i), w3i = SQ2H * (O3r - O3i);
                gr[0] = E0r + O0r; gi[0] = E0i + O0i;
                gr[4] = E0r - O0r; gi[4] = E0i - O0i;
                gr[1] = E1r + w1r; gi[1] = E1i + w1i;
                gr[5] = E1r - w1r; gi[5] = E1i - w1i;
                gr[2] = E2r + w2r; gi[2] = E2i + w2i;
                gr[6] = E2r - w2r; gi[6] = E2i - w2i;
                gr[3] = E3r + w3r; gi[3] = E3i + w3i;
                gr[7] = E3r - w3r; gi[7] = E3i - w3i;
            }
        }
        __syncthreads();   // reads done before relayout writes
        if (j < 5) {
            float* fr = s_fr + cc * 41 + j;
            float* fi = s_fi + cc * 41 + j;
#pragma unroll
            for (int yy = 0; yy < 8; yy++) { fr[yy * 5] = gr[yy]; fi[yy * 5] = gi[yy]; }
        }
    }
    __syncthreads();

    // -------- phase 3: inverse real row FFT (C2R) + store ------------------
    {
        const int c2 = tid & 63, y = tid >> 6;
        const float* fr = s_fr + c2 * 41 + y * 5;
        const float* fi = s_fi + c2 * 41 + y * 5;
        float G0r = fr[0];
        float G1r = fr[1], G1i = fi[1];
        float G2r = fr[2], G2i = fi[2];
        float G3r = fr[3], G3i = fi[3];
        float G4r = fr[4];
        float A1r = 2.f * G1r, A1i = 2.f * G1i;
        float A2r = 2.f * G2r, A2i = 2.f * G2i;
        float A3r = 2.f * G3r, A3i = 2.f * G3i;
        float B0 = G0r + G4r, B1 = G0r - G4r;
        float u = SQ2H * (A1r - A1i), v = SQ2H * (A3r + A3i);
        float p = SQ2H * (A1r + A1i), q = SQ2H * (A3r - A3i);
        float x0 = B0 + A1r + A2r + A3r;
        float x4 = B0 - A1r + A2r - A3r;
        float x2 = B0 - A2r - A1i + A3i;
        float x6 = B0 - A2r + A1i - A3i;
        float x1 = B1 + u - A2i - v;
        float x3 = B1 - p + A2i + q;
        float x5 = B1 - u - A2i + v;
        float x7 = B1 + p + A2i - q;
        float4* dst = reinterpret_cast<float4*>(
            g_mid + (((((size_t)b * 64 + c2) * 256) + hp * 8 + y) * 256 + wp * 8));
        dst[0] = make_float4(x0, x1, x2, x3);
        dst[1] = make_float4(x4, x5, x6, x7);
    }
}

// ---------------------------------------------------------------------------
// Kernel 2: 7x7 depthwise conv (pad 3) + GELU + 1x1 conv (64->32).
// Grid: (16, 16, 8). Block: 256 threads = 16x16 tile; 32 out-ch accumulators.
// ---------------------------------------------------------------------------
__global__ __launch_bounds__(256) void k2_dwout(
    const float* __restrict__ w_dw, const float* __restrict__ b_dw,
    const float* __restrict__ w_out, const float* __restrict__ b_out,
    float* __restrict__ out)
{
    __shared__ float s_halo[22 * 48];
    __shared__ float s_wdw[64 * 49];
    __shared__ float s_wout[64 * 33];   // [c2][co], padded
    __shared__ float s_bdw[64];
    __shared__ float s_bout[32];

    const int tid = threadIdx.x;
    for (int i = tid; i < 64 * 49; i += 256) s_wdw[i] = w_dw[i];
    for (int i = tid; i < 64 * 32; i += 256) {
        int co = i >> 6, c2 = i & 63;
        s_wout[c2 * 33 + co] = w_out[i];
    }
    if (tid < 64) s_bdw[tid] = b_dw[tid];
    if (tid < 32) s_bout[tid] = b_out[tid];

    const int ty = tid >> 4, tx = tid & 15;
    const int w0 = blockIdx.x << 4, h0 = blockIdx.y << 4, b = blockIdx.z;
    const float* midb = g_mid + (size_t)b * 64 * 65536;

    float acc[32];
#pragma unroll
    for (int co = 0; co < 32; co++) acc[co] = 0.f;

    for (int c2 = 0; c2 < 64; c2++) {
        __syncthreads();   // also covers weight-staging before first iter
        const float* src = midb + (size_t)c2 * 65536;
        for (int i = tid; i < 484; i += 256) {
            int r = i / 22, cl = i - r * 22;
            int hh = h0 - 3 + r, ww = w0 - 3 + cl;
            float val = 0.f;
            if ((unsigned)hh < 256u && (unsigned)ww < 256u)
                val = __ldg(src + hh * 256 + ww);
            s_halo[r * 48 + cl] = val;
        }
        __syncthreads();

        float v = s_bdw[c2];
        const float* wd = s_wdw + c2 * 49;
#pragma unroll
        for (int ky = 0; ky < 7; ky++) {
            const float* hrow = s_halo + (ty + ky) * 48 + tx;
#pragma unroll
            for (int kx = 0; kx < 7; kx++)
                v = fmaf(wd[ky * 7 + kx], hrow[kx], v);
        }
        float gv = v * normcdff(v);
        const float* wo = s_wout + c2 * 33;
#pragma unroll
        for (int co = 0; co < 32; co++)
            acc[co] = fmaf(wo[co], gv, acc[co]);
    }

    const int hh = h0 + ty, ww = w0 + tx;
    float* op = out + (size_t)b * 32 * 65536 + hh * 256 + ww;
#pragma unroll
    for (int co = 0; co < 32; co++)
        op[(size_t)co * 65536] = acc[co] + s_bout[co];
}

// ---------------------------------------------------------------------------
extern "C" void kernel_launch(void* const* d_in, const int* in_sizes, int n_in,
                              void* d_out, int out_size)
{
    const float* x     = (const float*)d_in[0];
    const float* w_in  = (const float*)d_in[1];
    const float* b_in  = (const float*)d_in[2];
    const float* fft1  = (const float*)d_in[3];
    const float* fft2  = (const float*)d_in[4];
    const float* w_dw  = (const float*)d_in[5];
    const float* b_dw  = (const float*)d_in[6];
    const float* w_out = (const float*)d_in[7];
    const float* b_out = (const float*)d_in[8];
    float* out = (float*)d_out;

    dim3 g1(1024, 8);
    k1_fft<<<g1, 512>>>(x, w_in, b_in, fft1, fft2);
    dim3 g2(16, 16, 8);
    k2_dwout<<<g2, 256>>>(w_dw, b_dw, w_out, b_out, out);
}